// round 2
// baseline (speedup 1.0000x reference)
#include <cuda_runtime.h>

#define DM    1024
#define HEADS 16
#define DK    64
#define BATCH 4
#define SEQ   2048
#define MTOK  (BATCH * SEQ)   // 8192

// Scratch (no cudaMalloc allowed): head-split projections + attention output.
__device__ float g_Q[(size_t)MTOK * DM];
__device__ float g_K[(size_t)MTOK * DM];
__device__ float g_V[(size_t)MTOK * DM];
__device__ float g_O[(size_t)MTOK * DM];

// ---------------------------------------------------------------------------
// SGEMM: C[M,N] = A[M,K] @ W[N,K]^T + bias[N]
// Tile 128x128x8, 256 threads, 8x8 per thread.
// HEADSPLIT=true writes C in [B, H, S, DK] layout (n = h*64 + dk, m = b*S + s).
// ---------------------------------------------------------------------------
template <bool HEADSPLIT>
__device__ __forceinline__ void sgemm_tile(const float* __restrict__ A,
                                           const float* __restrict__ W,
                                           const float* __restrict__ bias,
                                           float* __restrict__ C)
{
    __shared__ float As[8][132];
    __shared__ float Ws[8][132];

    const int tid = threadIdx.x;          // 0..255
    const int tx  = tid & 15;             // 0..15 (N dir)
    const int ty  = tid >> 4;             // 0..15 (M dir)
    const int m0  = blockIdx.y * 128;
    const int n0  = blockIdx.x * 128;

    const int lrow = tid >> 1;            // 0..127
    const int lcol = (tid & 1) * 4;       // 0 or 4

    const float* Ag = A + (size_t)(m0 + lrow) * DM + lcol;
    const float* Wg = W + (size_t)(n0 + lrow) * DM + lcol;

    float acc[8][8];
#pragma unroll
    for (int i = 0; i < 8; i++)
#pragma unroll
        for (int j = 0; j < 8; j++) acc[i][j] = 0.f;

    for (int kk = 0; kk < DM; kk += 8) {
        float4 a4 = *(const float4*)(Ag + kk);
        float4 w4 = *(const float4*)(Wg + kk);
        As[lcol + 0][lrow] = a4.x;
        As[lcol + 1][lrow] = a4.y;
        As[lcol + 2][lrow] = a4.z;
        As[lcol + 3][lrow] = a4.w;
        Ws[lcol + 0][lrow] = w4.x;
        Ws[lcol + 1][lrow] = w4.y;
        Ws[lcol + 2][lrow] = w4.z;
        Ws[lcol + 3][lrow] = w4.w;
        __syncthreads();

#pragma unroll
        for (int p = 0; p < 8; p++) {
            float4 a0 = *(const float4*)&As[p][ty * 8];
            float4 a1 = *(const float4*)&As[p][ty * 8 + 4];
            float4 b0 = *(const float4*)&Ws[p][tx * 8];
            float4 b1 = *(const float4*)&Ws[p][tx * 8 + 4];
            float ar[8] = {a0.x, a0.y, a0.z, a0.w, a1.x, a1.y, a1.z, a1.w};
            float br[8] = {b0.x, b0.y, b0.z, b0.w, b1.x, b1.y, b1.z, b1.w};
#pragma unroll
            for (int i = 0; i < 8; i++)
#pragma unroll
                for (int j = 0; j < 8; j++) acc[i][j] += ar[i] * br[j];
        }
        __syncthreads();
    }

    // Epilogue: add bias, store (two float4 per output row-fragment).
    const int nbase = n0 + tx * 8;
    float bv[8];
#pragma unroll
    for (int j = 0; j < 8; j++) bv[j] = bias[nbase + j];

#pragma unroll
    for (int i = 0; i < 8; i++) {
        const int m = m0 + ty * 8 + i;
        float r[8];
#pragma unroll
        for (int j = 0; j < 8; j++) r[j] = acc[i][j] + bv[j];

        float* dst;
        if (HEADSPLIT) {
            const int b_ = m >> 11;       // / SEQ
            const int s_ = m & (SEQ - 1);
            const int h  = nbase >> 6;    // all 8 cols within one head (8 | 64)
            const int dk = nbase & 63;
            dst = C + ((((size_t)b_ * HEADS + h) * SEQ) + s_) * DK + dk;
        } else {
            dst = C + (size_t)m * DM + nbase;
        }
        *(float4*)(dst + 0) = make_float4(r[0], r[1], r[2], r[3]);
        *(float4*)(dst + 4) = make_float4(r[4], r[5], r[6], r[7]);
    }
}

__global__ void __launch_bounds__(256) qkv_kernel(
    const float* __restrict__ q, const float* __restrict__ k, const float* __restrict__ v,
    const float* __restrict__ wq, const float* __restrict__ bq,
    const float* __restrict__ wk, const float* __restrict__ bk,
    const float* __restrict__ wv, const float* __restrict__ bv)
{
    if (blockIdx.z == 0)      sgemm_tile<true>(q, wq, bq, g_Q);
    else if (blockIdx.z == 1) sgemm_tile<true>(k, wk, bk, g_K);
    else                      sgemm_tile<true>(v, wv, bv, g_V);
}

__global__ void __launch_bounds__(256) out_kernel(
    const float* __restrict__ wo, const float* __restrict__ bo, float* __restrict__ out)
{
    sgemm_tile<false>(g_O, wo, bo, out);
}

// ---------------------------------------------------------------------------
// Causal flash attention, fp32.
// Block = 128 threads, one query row per thread (BQ=128). K/V streamed in
// BK=32 row tiles through shared memory (float4 layout). Online softmax.
// q pre-scaled by 1/sqrt(DK). Writes g_O in [B, S, D] layout.
// ---------------------------------------------------------------------------
__global__ void __launch_bounds__(128) attn_kernel()
{
    constexpr int   BQ      = 128;
    constexpr int   BKT     = 32;
    constexpr float QK_SCALE = 0.125f;   // 1/sqrt(DK)

    __shared__ float4 Ks[BKT * 16];   // 32 rows x 64 floats
    __shared__ float4 Vs[BKT * 16];

    const int b   = blockIdx.z;
    const int h   = blockIdx.y;
    const int q0  = blockIdx.x * BQ;
    const int tid = threadIdx.x;
    const int qrow = q0 + tid;

    const float* Qp = g_Q + (((size_t)(b * HEADS + h)) * SEQ + qrow) * DK;
    float qv[DK];
#pragma unroll
    for (int i = 0; i < 16; i++) {
        float4 t4 = ((const float4*)Qp)[i];
        qv[4 * i + 0] = t4.x * QK_SCALE;
        qv[4 * i + 1] = t4.y * QK_SCALE;
        qv[4 * i + 2] = t4.z * QK_SCALE;
        qv[4 * i + 3] = t4.w * QK_SCALE;
    }

    float acc[DK];
#pragma unroll
    for (int i = 0; i < DK; i++) acc[i] = 0.f;
    float mrun = -1e30f, lrun = 0.f;

    const float4* Kb = (const float4*)(g_K + ((size_t)(b * HEADS + h)) * SEQ * DK);
    const float4* Vb = (const float4*)(g_V + ((size_t)(b * HEADS + h)) * SEQ * DK);

    const int ntiles = (q0 + BQ) / BKT;   // causal: only tiles with any live key

    for (int t = 0; t < ntiles; t++) {
        __syncthreads();
        const float4* Kt = Kb + t * (BKT * 16);
        const float4* Vt = Vb + t * (BKT * 16);
#pragma unroll
        for (int i = 0; i < 4; i++) {
            Ks[tid + i * 128] = Kt[tid + i * 128];
            Vs[tid + i * 128] = Vt[tid + i * 128];
        }
        __syncthreads();

        const int kmax = qrow - t * BKT;  // j <= kmax is unmasked

        float p[BKT];
        float mnew = mrun;
#pragma unroll
        for (int j = 0; j < BKT; j++) {
            const float4* krow = &Ks[j * 16];
            float s = 0.f;
#pragma unroll
            for (int d4 = 0; d4 < 16; d4++) {
                float4 kk = krow[d4];
                s += qv[4 * d4 + 0] * kk.x;
                s += qv[4 * d4 + 1] * kk.y;
                s += qv[4 * d4 + 2] * kk.z;
                s += qv[4 * d4 + 3] * kk.w;
            }
            s = (j <= kmax) ? s : -1e30f;
            p[j] = s;
            mnew = fmaxf(mnew, s);
        }

        const float alpha = __expf(mrun - mnew);
        lrun *= alpha;
#pragma unroll
        for (int i = 0; i < DK; i++) acc[i] *= alpha;

#pragma unroll
        for (int j = 0; j < BKT; j++) {
            const float pj = __expf(p[j] - mnew);
            lrun += pj;
            const float4* vrow = &Vs[j * 16];
#pragma unroll
            for (int d4 = 0; d4 < 16; d4++) {
                float4 vv = vrow[d4];
                acc[4 * d4 + 0] += pj * vv.x;
                acc[4 * d4 + 1] += pj * vv.y;
                acc[4 * d4 + 2] += pj * vv.z;
                acc[4 * d4 + 3] += pj * vv.w;
            }
        }
        mrun = mnew;
    }

    const float inv = 1.0f / lrun;
    float* Op = g_O + ((size_t)(b * SEQ + qrow)) * DM + h * DK;
#pragma unroll
    for (int i = 0; i < 16; i++) {
        float4 o4 = make_float4(acc[4 * i + 0] * inv, acc[4 * i + 1] * inv,
                                acc[4 * i + 2] * inv, acc[4 * i + 3] * inv);
        ((float4*)Op)[i] = o4;
    }
}

// ---------------------------------------------------------------------------
// d_in order (metadata): 0=q 1=k 2=v 3=mask 4=wq 5=bq 6=wk 7=bk 8=wv 9=bv 10=wo 11=bo
// mask is a known causal tril — handled analytically, not read.
// ---------------------------------------------------------------------------
extern "C" void kernel_launch(void* const* d_in, const int* in_sizes, int n_in,
                              void* d_out, int out_size)
{
    const float* q  = (const float*)d_in[0];
    const float* k  = (const float*)d_in[1];
    const float* v  = (const float*)d_in[2];
    const float* wq = (const float*)d_in[4];
    const float* bq = (const float*)d_in[5];
    const float* wk = (const float*)d_in[6];
    const float* bk = (const float*)d_in[7];
    const float* wv = (const float*)d_in[8];
    const float* bv = (const float*)d_in[9];
    const float* wo = (const float*)d_in[10];
    const float* bo = (const float*)d_in[11];
    float* out = (float*)d_out;

    dim3 g1(DM / 128, MTOK / 128, 3);          // 8 x 64 x 3
    qkv_kernel<<<g1, 256>>>(q, k, v, wq, bq, wk, bk, wv, bv);

    dim3 g2(SEQ / 128, HEADS, BATCH);          // 16 x 16 x 4
    attn_kernel<<<g2, 128>>>();

    dim3 g3(DM / 128, MTOK / 128, 1);          // 8 x 64
    out_kernel<<<g3, 256>>>(wo, bo, out);
}

// round 5
// speedup vs baseline: 1.4720x; 1.4720x over previous
#include <cuda_runtime.h>
#include <cuda_bf16.h>
#include <cstdint>

#define DM    1024
#define HEADS 16
#define DK    64
#define BATCH 4
#define SEQ   2048
#define MTOK  (BATCH * SEQ)   // 8192

// ---------------------------------------------------------------------------
// Scratch (no cudaMalloc allowed)
// ---------------------------------------------------------------------------
__device__ float g_Q[(size_t)MTOK * DM];
__device__ float g_K[(size_t)MTOK * DM];
__device__ float g_V[(size_t)MTOK * DM];
__device__ float g_O[(size_t)MTOK * DM];

// bf16 hi/lo splits of activations and weights
__device__ __align__(16) __nv_bfloat16 g_qh[(size_t)MTOK * DM];
__device__ __align__(16) __nv_bfloat16 g_ql[(size_t)MTOK * DM];
__device__ __align__(16) __nv_bfloat16 g_kh[(size_t)MTOK * DM];
__device__ __align__(16) __nv_bfloat16 g_kl[(size_t)MTOK * DM];
__device__ __align__(16) __nv_bfloat16 g_vh[(size_t)MTOK * DM];
__device__ __align__(16) __nv_bfloat16 g_vl[(size_t)MTOK * DM];
__device__ __align__(16) __nv_bfloat16 g_oh[(size_t)MTOK * DM];
__device__ __align__(16) __nv_bfloat16 g_ol[(size_t)MTOK * DM];
__device__ __align__(16) __nv_bfloat16 g_wqh[(size_t)DM * DM];
__device__ __align__(16) __nv_bfloat16 g_wql[(size_t)DM * DM];
__device__ __align__(16) __nv_bfloat16 g_wkh[(size_t)DM * DM];
__device__ __align__(16) __nv_bfloat16 g_wkl[(size_t)DM * DM];
__device__ __align__(16) __nv_bfloat16 g_wvh[(size_t)DM * DM];
__device__ __align__(16) __nv_bfloat16 g_wvl[(size_t)DM * DM];
__device__ __align__(16) __nv_bfloat16 g_woh[(size_t)DM * DM];
__device__ __align__(16) __nv_bfloat16 g_wol[(size_t)DM * DM];

// ---------------------------------------------------------------------------
// PTX helpers (sm_80-compatible path only: cp.async + ldmatrix + mma.sync)
// ---------------------------------------------------------------------------
__device__ __forceinline__ uint32_t smem_to_u32(const void* p) {
    uint32_t a;
    asm("{ .reg .u64 t; cvta.to.shared.u64 t, %1; cvt.u32.u64 %0, t; }" : "=r"(a) : "l"(p));
    return a;
}

#define CP_ASYNC16(saddr, gptr) \
    asm volatile("cp.async.cg.shared.global [%0], [%1], 16;" :: "r"(saddr), "l"(gptr))
#define CP_COMMIT()  asm volatile("cp.async.commit_group;" ::: "memory")
#define CP_WAIT1()   asm volatile("cp.async.wait_group 1;" ::: "memory")
#define CP_WAIT0()   asm volatile("cp.async.wait_group 0;" ::: "memory")

#define LDSM_X4(r0, r1, r2, r3, addr) \
    asm volatile("ldmatrix.sync.aligned.m8n8.x4.shared.b16 {%0,%1,%2,%3}, [%4];" \
        : "=r"(r0), "=r"(r1), "=r"(r2), "=r"(r3) : "r"(addr))

#define MMA_BF16(d, a, b0, b1) \
    asm volatile("mma.sync.aligned.m16n8k16.row.col.f32.bf16.bf16.f32 " \
        "{%0,%1,%2,%3}, {%4,%5,%6,%7}, {%8,%9}, {%0,%1,%2,%3};" \
        : "+f"((d)[0]), "+f"((d)[1]), "+f"((d)[2]), "+f"((d)[3]) \
        : "r"((a)[0]), "r"((a)[1]), "r"((a)[2]), "r"((a)[3]), "r"(b0), "r"(b1))

// ---------------------------------------------------------------------------
// fp32 -> bf16 hi/lo split, 4 elems/thread
// ---------------------------------------------------------------------------
__global__ void __launch_bounds__(256) split_kernel(const float* __restrict__ x,
                                                    __nv_bfloat16* __restrict__ hi,
                                                    __nv_bfloat16* __restrict__ lo, int n4)
{
    int i = blockIdx.x * blockDim.x + threadIdx.x;
    if (i >= n4) return;
    float4 v = ((const float4*)x)[i];
    __nv_bfloat16 h0 = __float2bfloat16(v.x), h1 = __float2bfloat16(v.y);
    __nv_bfloat16 h2 = __float2bfloat16(v.z), h3 = __float2bfloat16(v.w);
    __nv_bfloat16 l0 = __float2bfloat16(v.x - __bfloat162float(h0));
    __nv_bfloat16 l1 = __float2bfloat16(v.y - __bfloat162float(h1));
    __nv_bfloat16 l2 = __float2bfloat16(v.z - __bfloat162float(h2));
    __nv_bfloat16 l3 = __float2bfloat16(v.w - __bfloat162float(h3));
    __nv_bfloat162 hp0 = __nv_bfloat162(h0, h1), hp1 = __nv_bfloat162(h2, h3);
    __nv_bfloat162 lp0 = __nv_bfloat162(l0, l1), lp1 = __nv_bfloat162(l2, l3);
    uint2 hw, lw;
    hw.x = *(uint32_t*)&hp0; hw.y = *(uint32_t*)&hp1;
    lw.x = *(uint32_t*)&lp0; lw.y = *(uint32_t*)&lp1;
    ((uint2*)hi)[i] = hw;
    ((uint2*)lo)[i] = lw;
}

// ---------------------------------------------------------------------------
// mma.sync bf16x3 GEMM:  C[M,N] = Ah*Bh^T + Ah*Bl^T + Al*Bh^T + bias
// Tile 128x128, 8 warps (each 64x32), BK=32, cp.async double buffer.
// SMEM per buffer: Ah | Al | Bh | Bl, each 128x32 bf16 = 8 KB. 2 x 32 KB.
// 16B-chunk XOR swizzle: chunk' = chunk ^ ((row>>1)&3)  (conflict-free ldmatrix)
// ---------------------------------------------------------------------------
#define GEMM_SMEM_BYTES 65536

__device__ __forceinline__ uint32_t sw_off(int row, int c)
{
    return (uint32_t)((row * 4 + (c ^ ((row >> 1) & 3))) * 16);
}

__device__ __forceinline__ void load_stage(uint32_t sbuf,
    const __nv_bfloat16* __restrict__ A_h, const __nv_bfloat16* __restrict__ A_l,
    const __nv_bfloat16* __restrict__ B_h, const __nv_bfloat16* __restrict__ B_l,
    int m0, int n0, int kk, int tid)
{
#pragma unroll
    for (int i = 0; i < 2; i++) {
        const int idx = tid + i * 256;      // 0..511 chunk id per tile
        const int row = idx >> 2;
        const int c   = idx & 3;
        const uint32_t so = sw_off(row, c);
        const size_t aoff = (size_t)(m0 + row) * DM + kk + c * 8;
        const size_t boff = (size_t)(n0 + row) * DM + kk + c * 8;
        CP_ASYNC16(sbuf + so,          A_h + aoff);
        CP_ASYNC16(sbuf + 8192  + so,  A_l + aoff);
        CP_ASYNC16(sbuf + 16384 + so,  B_h + boff);
        CP_ASYNC16(sbuf + 24576 + so,  B_l + boff);
    }
}

template <bool HS>
__global__ void __launch_bounds__(256) gemm_bf3(const __nv_bfloat16* __restrict__ Ah,
                                                const __nv_bfloat16* __restrict__ Al,
                                                const __nv_bfloat16* __restrict__ Bh,
                                                const __nv_bfloat16* __restrict__ Bl,
                                                const float* __restrict__ bias,
                                                float* __restrict__ C)
{
    extern __shared__ char smem[];
    const uint32_t sbase = smem_to_u32(smem);
    const int tid   = threadIdx.x;
    const int lane  = tid & 31;
    const int wid   = tid >> 5;
    const int warpM = wid >> 2;          // 0..1
    const int warpN = wid & 3;           // 0..3
    const int m0 = blockIdx.y * 128;
    const int n0 = blockIdx.x * 128;

    float acc[4][4][4];
#pragma unroll
    for (int a = 0; a < 4; a++)
#pragma unroll
        for (int b = 0; b < 4; b++)
#pragma unroll
            for (int c = 0; c < 4; c++) acc[a][b][c] = 0.f;

    // prologue
    load_stage(sbase, Ah, Al, Bh, Bl, m0, n0, 0, tid);
    CP_COMMIT();

    // ldmatrix lane addressing (constant across stages)
    const int arow_l = warpM * 64 + (lane & 15);        // + 16*mt
    const int ac_l   = (lane >> 4);                     // + 2*ks
    const int brow_l = warpN * 32 + (lane & 7) + ((lane >> 4) << 3);  // + 16*np
    const int bc_l   = ((lane >> 3) & 1);               // + 2*ks

#pragma unroll 1
    for (int s = 0; s < 32; s++) {
        const uint32_t sbuf = sbase + (uint32_t)(s & 1) * 32768u;
        if (s + 1 < 32) {
            load_stage(sbase + (uint32_t)((s + 1) & 1) * 32768u,
                       Ah, Al, Bh, Bl, m0, n0, (s + 1) * 32, tid);
            CP_COMMIT();
            CP_WAIT1();
        } else {
            CP_WAIT0();
        }
        __syncthreads();

#pragma unroll
        for (int ks = 0; ks < 2; ks++) {
            uint32_t ahf[4][4], alf[4][4], bhf[2][4], blf[2][4];
            const int ac = ks * 2 + ac_l;
#pragma unroll
            for (int mt = 0; mt < 4; mt++) {
                const uint32_t so = sw_off(arow_l + 16 * mt, ac);
                LDSM_X4(ahf[mt][0], ahf[mt][1], ahf[mt][2], ahf[mt][3], sbuf + so);
                LDSM_X4(alf[mt][0], alf[mt][1], alf[mt][2], alf[mt][3], sbuf + 8192 + so);
            }
            const int bc = ks * 2 + bc_l;
#pragma unroll
            for (int np = 0; np < 2; np++) {
                const uint32_t so = sw_off(brow_l + 16 * np, bc);
                LDSM_X4(bhf[np][0], bhf[np][1], bhf[np][2], bhf[np][3], sbuf + 16384 + so);
                LDSM_X4(blf[np][0], blf[np][1], blf[np][2], blf[np][3], sbuf + 24576 + so);
            }
#pragma unroll
            for (int mt = 0; mt < 4; mt++) {
#pragma unroll
                for (int nt = 0; nt < 4; nt++) {
                    const int np = nt >> 1;
                    const int q  = (nt & 1) * 2;
                    MMA_BF16(acc[mt][nt], ahf[mt], bhf[np][q], bhf[np][q + 1]);
                    MMA_BF16(acc[mt][nt], ahf[mt], blf[np][q], blf[np][q + 1]);
                    MMA_BF16(acc[mt][nt], alf[mt], bhf[np][q], bhf[np][q + 1]);
                }
            }
        }
        __syncthreads();
    }

    // epilogue: add bias, scatter (HS: [B,H,S,DK] layout)
    const int mbase = m0 + warpM * 64;
#pragma unroll
    for (int nt = 0; nt < 4; nt++) {
        const int col = n0 + warpN * 32 + nt * 8 + 2 * (lane & 3);
        const float b0 = bias[col];
        const float b1 = bias[col + 1];
#pragma unroll
        for (int mt = 0; mt < 4; mt++) {
            const int r0 = mbase + mt * 16 + (lane >> 2);
#pragma unroll
            for (int half = 0; half < 2; half++) {
                const int m = r0 + half * 8;
                float* dst;
                if (HS) {
                    const int b_ = m >> 11;
                    const int s_ = m & (SEQ - 1);
                    const int h  = col >> 6;
                    const int dk = col & 63;
                    dst = C + ((((size_t)b_ * HEADS + h) * SEQ) + s_) * DK + dk;
                } else {
                    dst = C + (size_t)m * DM + col;
                }
                float2 o;
                o.x = acc[mt][nt][half * 2 + 0] + b0;
                o.y = acc[mt][nt][half * 2 + 1] + b1;
                *(float2*)dst = o;
            }
        }
    }
}

// ---------------------------------------------------------------------------
// Causal flash attention, fp32 (unchanged from passing round-2 kernel)
// ---------------------------------------------------------------------------
__global__ void __launch_bounds__(128) attn_kernel()
{
    constexpr int   BQ = 128;
    constexpr int   BKT = 32;
    constexpr float QK_SCALE = 0.125f;

    __shared__ float4 Ks[BKT * 16];
    __shared__ float4 Vs[BKT * 16];

    const int b   = blockIdx.z;
    const int h   = blockIdx.y;
    const int q0  = blockIdx.x * BQ;
    const int tid = threadIdx.x;
    const int qrow = q0 + tid;

    const float* Qp = g_Q + (((size_t)(b * HEADS + h)) * SEQ + qrow) * DK;
    float qv[DK];
#pragma unroll
    for (int i = 0; i < 16; i++) {
        float4 t4 = ((const float4*)Qp)[i];
        qv[4 * i + 0] = t4.x * QK_SCALE;
        qv[4 * i + 1] = t4.y * QK_SCALE;
        qv[4 * i + 2] = t4.z * QK_SCALE;
        qv[4 * i + 3] = t4.w * QK_SCALE;
    }

    float acc[DK];
#pragma unroll
    for (int i = 0; i < DK; i++) acc[i] = 0.f;
    float mrun = -1e30f, lrun = 0.f;

    const float4* Kb = (const float4*)(g_K + ((size_t)(b * HEADS + h)) * SEQ * DK);
    const float4* Vb = (const float4*)(g_V + ((size_t)(b * HEADS + h)) * SEQ * DK);

    const int ntiles = (q0 + BQ) / BKT;

    for (int t = 0; t < ntiles; t++) {
        __syncthreads();
        const float4* Kt = Kb + t * (BKT * 16);
        const float4* Vt = Vb + t * (BKT * 16);
#pragma unroll
        for (int i = 0; i < 4; i++) {
            Ks[tid + i * 128] = Kt[tid + i * 128];
            Vs[tid + i * 128] = Vt[tid + i * 128];
        }
        __syncthreads();

        const int kmax = qrow - t * BKT;

        float p[BKT];
        float mnew = mrun;
#pragma unroll
        for (int j = 0; j < BKT; j++) {
            const float4* krow = &Ks[j * 16];
            float s = 0.f;
#pragma unroll
            for (int d4 = 0; d4 < 16; d4++) {
                float4 kk = krow[d4];
                s += qv[4 * d4 + 0] * kk.x;
                s += qv[4 * d4 + 1] * kk.y;
                s += qv[4 * d4 + 2] * kk.z;
                s += qv[4 * d4 + 3] * kk.w;
            }
            s = (j <= kmax) ? s : -1e30f;
            p[j] = s;
            mnew = fmaxf(mnew, s);
        }

        const float alpha = __expf(mrun - mnew);
        lrun *= alpha;
#pragma unroll
        for (int i = 0; i < DK; i++) acc[i] *= alpha;

#pragma unroll
        for (int j = 0; j < BKT; j++) {
            const float pj = __expf(p[j] - mnew);
            lrun += pj;
            const float4* vrow = &Vs[j * 16];
#pragma unroll
            for (int d4 = 0; d4 < 16; d4++) {
                float4 vv = vrow[d4];
                acc[4 * d4 + 0] += pj * vv.x;
                acc[4 * d4 + 1] += pj * vv.y;
                acc[4 * d4 + 2] += pj * vv.z;
                acc[4 * d4 + 3] += pj * vv.w;
            }
        }
        mrun = mnew;
    }

    const float inv = 1.0f / lrun;
    float* Op = g_O + ((size_t)(b * SEQ + qrow)) * DM + h * DK;
#pragma unroll
    for (int i = 0; i < 16; i++) {
        float4 o4 = make_float4(acc[4 * i + 0] * inv, acc[4 * i + 1] * inv,
                                acc[4 * i + 2] * inv, acc[4 * i + 3] * inv);
        ((float4*)Op)[i] = o4;
    }
}

// ---------------------------------------------------------------------------
// d_in order: 0=q 1=k 2=v 3=mask 4=wq 5=bq 6=wk 7=bk 8=wv 9=bv 10=wo 11=bo
// ---------------------------------------------------------------------------
extern "C" void kernel_launch(void* const* d_in, const int* in_sizes, int n_in,
                              void* d_out, int out_size)
{
    const float* q  = (const float*)d_in[0];
    const float* k  = (const float*)d_in[1];
    const float* v  = (const float*)d_in[2];
    const float* wq = (const float*)d_in[4];
    const float* bq = (const float*)d_in[5];
    const float* wk = (const float*)d_in[6];
    const float* bk = (const float*)d_in[7];
    const float* wv = (const float*)d_in[8];
    const float* bv = (const float*)d_in[9];
    const float* wo = (const float*)d_in[10];
    const float* bo = (const float*)d_in[11];
    float* out = (float*)d_out;

    // Unconditional every call (no static guards — harness rule). Not a stream
    // op, so it is graph-capture-safe.
    cudaFuncSetAttribute(gemm_bf3<true>,  cudaFuncAttributeMaxDynamicSharedMemorySize, GEMM_SMEM_BYTES);
    cudaFuncSetAttribute(gemm_bf3<false>, cudaFuncAttributeMaxDynamicSharedMemorySize, GEMM_SMEM_BYTES);

    __nv_bfloat16 *qh, *ql, *kh, *kl, *vh, *vl, *oh, *ol;
    __nv_bfloat16 *wqh, *wql, *wkh, *wkl, *wvh, *wvl, *woh, *wol;
    float *gO, *dQ, *dK, *dV;
    cudaGetSymbolAddress((void**)&qh,  g_qh);  cudaGetSymbolAddress((void**)&ql,  g_ql);
    cudaGetSymbolAddress((void**)&kh,  g_kh);  cudaGetSymbolAddress((void**)&kl,  g_kl);
    cudaGetSymbolAddress((void**)&vh,  g_vh);  cudaGetSymbolAddress((void**)&vl,  g_vl);
    cudaGetSymbolAddress((void**)&oh,  g_oh);  cudaGetSymbolAddress((void**)&ol,  g_ol);
    cudaGetSymbolAddress((void**)&wqh, g_wqh); cudaGetSymbolAddress((void**)&wql, g_wql);
    cudaGetSymbolAddress((void**)&wkh, g_wkh); cudaGetSymbolAddress((void**)&wkl, g_wkl);
    cudaGetSymbolAddress((void**)&wvh, g_wvh); cudaGetSymbolAddress((void**)&wvl, g_wvl);
    cudaGetSymbolAddress((void**)&woh, g_woh); cudaGetSymbolAddress((void**)&wol, g_wol);
    cudaGetSymbolAddress((void**)&gO,  g_O);
    cudaGetSymbolAddress((void**)&dQ,  g_Q);
    cudaGetSymbolAddress((void**)&dK,  g_K);
    cudaGetSymbolAddress((void**)&dV,  g_V);

    const int nAct4 = MTOK * DM / 4;   // 2,097,152
    const int nW4   = DM * DM / 4;     // 262,144

    split_kernel<<<nAct4 / 256, 256>>>(q,  qh,  ql,  nAct4);
    split_kernel<<<nAct4 / 256, 256>>>(k,  kh,  kl,  nAct4);
    split_kernel<<<nAct4 / 256, 256>>>(v,  vh,  vl,  nAct4);
    split_kernel<<<nW4 / 256, 256>>>(wq, wqh, wql, nW4);
    split_kernel<<<nW4 / 256, 256>>>(wk, wkh, wkl, nW4);
    split_kernel<<<nW4 / 256, 256>>>(wv, wvh, wvl, nW4);
    split_kernel<<<nW4 / 256, 256>>>(wo, woh, wol, nW4);

    dim3 gg(DM / 128, MTOK / 128);     // 8 x 64
    gemm_bf3<true><<<gg, 256, GEMM_SMEM_BYTES>>>(qh, ql, wqh, wql, bq, dQ);
    gemm_bf3<true><<<gg, 256, GEMM_SMEM_BYTES>>>(kh, kl, wkh, wkl, bk, dK);
    gemm_bf3<true><<<gg, 256, GEMM_SMEM_BYTES>>>(vh, vl, wvh, wvl, bv, dV);

    dim3 ga(SEQ / 128, HEADS, BATCH);  // 16 x 16 x 4
    attn_kernel<<<ga, 128>>>();

    split_kernel<<<nAct4 / 256, 256>>>(gO, oh, ol, nAct4);
    gemm_bf3<false><<<gg, 256, GEMM_SMEM_BYTES>>>(oh, ol, woh, wol, bo, out);
}

// round 8
// speedup vs baseline: 3.8075x; 2.5867x over previous
#include <cuda_runtime.h>
#include <cuda_bf16.h>
#include <cstdint>

#define DM    1024
#define HEADS 16
#define DK    64
#define BATCH 4
#define SEQ   2048
#define MTOK  (BATCH * SEQ)   // 8192

// ---------------------------------------------------------------------------
// Scratch (no cudaMalloc allowed)
// ---------------------------------------------------------------------------
// input splits (token-major [tok][DM])
__device__ __align__(16) __nv_bfloat16 g_qh[(size_t)MTOK * DM];
__device__ __align__(16) __nv_bfloat16 g_ql[(size_t)MTOK * DM];
__device__ __align__(16) __nv_bfloat16 g_kh[(size_t)MTOK * DM];
__device__ __align__(16) __nv_bfloat16 g_kl[(size_t)MTOK * DM];
__device__ __align__(16) __nv_bfloat16 g_vh[(size_t)MTOK * DM];
__device__ __align__(16) __nv_bfloat16 g_vl[(size_t)MTOK * DM];
// attention output splits (token-major [tok][DM])
__device__ __align__(16) __nv_bfloat16 g_oh[(size_t)MTOK * DM];
__device__ __align__(16) __nv_bfloat16 g_ol[(size_t)MTOK * DM];
// projected Q/K/V splits (head-split [B,H,S,DK])
__device__ __align__(16) __nv_bfloat16 g_Qh[(size_t)MTOK * DM];
__device__ __align__(16) __nv_bfloat16 g_Ql[(size_t)MTOK * DM];
__device__ __align__(16) __nv_bfloat16 g_Kh[(size_t)MTOK * DM];
__device__ __align__(16) __nv_bfloat16 g_Kl[(size_t)MTOK * DM];
__device__ __align__(16) __nv_bfloat16 g_Vh[(size_t)MTOK * DM];
__device__ __align__(16) __nv_bfloat16 g_Vl[(size_t)MTOK * DM];
// weight splits
__device__ __align__(16) __nv_bfloat16 g_wqh[(size_t)DM * DM];
__device__ __align__(16) __nv_bfloat16 g_wql[(size_t)DM * DM];
__device__ __align__(16) __nv_bfloat16 g_wkh[(size_t)DM * DM];
__device__ __align__(16) __nv_bfloat16 g_wkl[(size_t)DM * DM];
__device__ __align__(16) __nv_bfloat16 g_wvh[(size_t)DM * DM];
__device__ __align__(16) __nv_bfloat16 g_wvl[(size_t)DM * DM];
__device__ __align__(16) __nv_bfloat16 g_woh[(size_t)DM * DM];
__device__ __align__(16) __nv_bfloat16 g_wol[(size_t)DM * DM];

// ---------------------------------------------------------------------------
// PTX helpers (sm_80-compatible: cp.async + ldmatrix + mma.sync)
// ---------------------------------------------------------------------------
__device__ __forceinline__ uint32_t smem_to_u32(const void* p) {
    uint32_t a;
    asm("{ .reg .u64 t; cvta.to.shared.u64 t, %1; cvt.u32.u64 %0, t; }" : "=r"(a) : "l"(p));
    return a;
}

#define CP_ASYNC16(saddr, gptr) \
    asm volatile("cp.async.cg.shared.global [%0], [%1], 16;" :: "r"(saddr), "l"(gptr))
#define CP_COMMIT()  asm volatile("cp.async.commit_group;" ::: "memory")
#define CP_WAIT1()   asm volatile("cp.async.wait_group 1;" ::: "memory")
#define CP_WAIT0()   asm volatile("cp.async.wait_group 0;" ::: "memory")

#define LDSM_X4(r0, r1, r2, r3, addr) \
    asm volatile("ldmatrix.sync.aligned.m8n8.x4.shared.b16 {%0,%1,%2,%3}, [%4];" \
        : "=r"(r0), "=r"(r1), "=r"(r2), "=r"(r3) : "r"(addr))
#define LDSM_X4_T(r0, r1, r2, r3, addr) \
    asm volatile("ldmatrix.sync.aligned.m8n8.x4.trans.shared.b16 {%0,%1,%2,%3}, [%4];" \
        : "=r"(r0), "=r"(r1), "=r"(r2), "=r"(r3) : "r"(addr))

#define MMA_BF16(d, a, b0, b1) \
    asm volatile("mma.sync.aligned.m16n8k16.row.col.f32.bf16.bf16.f32 " \
        "{%0,%1,%2,%3}, {%4,%5,%6,%7}, {%8,%9}, {%0,%1,%2,%3};" \
        : "+f"((d)[0]), "+f"((d)[1]), "+f"((d)[2]), "+f"((d)[3]) \
        : "r"((a)[0]), "r"((a)[1]), "r"((a)[2]), "r"((a)[3]), "r"(b0), "r"(b1))

// pack two floats into bf16x2 hi + lo-residual words
__device__ __forceinline__ void split2(float x, float y, uint32_t& h, uint32_t& l)
{
    __nv_bfloat16 hx = __float2bfloat16(x), hy = __float2bfloat16(y);
    __nv_bfloat16 lx = __float2bfloat16(x - __bfloat162float(hx));
    __nv_bfloat16 ly = __float2bfloat16(y - __bfloat162float(hy));
    __nv_bfloat162 hp(hx, hy), lp(lx, ly);
    h = *(uint32_t*)&hp;
    l = *(uint32_t*)&lp;
}

// ---------------------------------------------------------------------------
// fp32 -> bf16 hi/lo split, 4 elems/thread
// ---------------------------------------------------------------------------
__global__ void __launch_bounds__(256) split_kernel(const float* __restrict__ x,
                                                    __nv_bfloat16* __restrict__ hi,
                                                    __nv_bfloat16* __restrict__ lo, int n4)
{
    int i = blockIdx.x * blockDim.x + threadIdx.x;
    if (i >= n4) return;
    float4 v = ((const float4*)x)[i];
    uint2 hw, lw;
    split2(v.x, v.y, hw.x, lw.x);
    split2(v.z, v.w, hw.y, lw.y);
    ((uint2*)hi)[i] = hw;
    ((uint2*)lo)[i] = lw;
}

// ---------------------------------------------------------------------------
// mma.sync bf16x3 GEMM:  C = Ah*Bh^T + Ah*Bl^T + Al*Bh^T + bias
// Tile 128x128, 8 warps, BK=32, cp.async double buffer.
// HS=true : write bf16 hi/lo pairs, head-split [B,H,S,DK] layout (Ch, Cl)
// HS=false: write fp32, token-major [m][DM] (Cf)
// ---------------------------------------------------------------------------
#define GEMM_SMEM_BYTES 65536

__device__ __forceinline__ uint32_t sw_off(int row, int c)
{
    return (uint32_t)((row * 4 + (c ^ ((row >> 1) & 3))) * 16);
}

__device__ __forceinline__ void load_stage(uint32_t sbuf,
    const __nv_bfloat16* __restrict__ A_h, const __nv_bfloat16* __restrict__ A_l,
    const __nv_bfloat16* __restrict__ B_h, const __nv_bfloat16* __restrict__ B_l,
    int m0, int n0, int kk, int tid)
{
#pragma unroll
    for (int i = 0; i < 2; i++) {
        const int idx = tid + i * 256;
        const int row = idx >> 2;
        const int c   = idx & 3;
        const uint32_t so = sw_off(row, c);
        const size_t aoff = (size_t)(m0 + row) * DM + kk + c * 8;
        const size_t boff = (size_t)(n0 + row) * DM + kk + c * 8;
        CP_ASYNC16(sbuf + so,          A_h + aoff);
        CP_ASYNC16(sbuf + 8192  + so,  A_l + aoff);
        CP_ASYNC16(sbuf + 16384 + so,  B_h + boff);
        CP_ASYNC16(sbuf + 24576 + so,  B_l + boff);
    }
}

template <bool HS>
__global__ void __launch_bounds__(256) gemm_bf3(const __nv_bfloat16* __restrict__ Ah,
                                                const __nv_bfloat16* __restrict__ Al,
                                                const __nv_bfloat16* __restrict__ Bh,
                                                const __nv_bfloat16* __restrict__ Bl,
                                                const float* __restrict__ bias,
                                                __nv_bfloat16* __restrict__ Ch,
                                                __nv_bfloat16* __restrict__ Cl,
                                                float* __restrict__ Cf)
{
    extern __shared__ char smem[];
    const uint32_t sbase = smem_to_u32(smem);
    const int tid   = threadIdx.x;
    const int lane  = tid & 31;
    const int wid   = tid >> 5;
    const int warpM = wid >> 2;
    const int warpN = wid & 3;
    const int m0 = blockIdx.y * 128;
    const int n0 = blockIdx.x * 128;

    float acc[4][4][4];
#pragma unroll
    for (int a = 0; a < 4; a++)
#pragma unroll
        for (int b = 0; b < 4; b++)
#pragma unroll
            for (int c = 0; c < 4; c++) acc[a][b][c] = 0.f;

    load_stage(sbase, Ah, Al, Bh, Bl, m0, n0, 0, tid);
    CP_COMMIT();

    const int arow_l = warpM * 64 + (lane & 15);
    const int ac_l   = (lane >> 4);
    const int brow_l = warpN * 32 + (lane & 7) + ((lane >> 4) << 3);
    const int bc_l   = ((lane >> 3) & 1);

#pragma unroll 1
    for (int s = 0; s < 32; s++) {
        const uint32_t sbuf = sbase + (uint32_t)(s & 1) * 32768u;
        if (s + 1 < 32) {
            load_stage(sbase + (uint32_t)((s + 1) & 1) * 32768u,
                       Ah, Al, Bh, Bl, m0, n0, (s + 1) * 32, tid);
            CP_COMMIT();
            CP_WAIT1();
        } else {
            CP_WAIT0();
        }
        __syncthreads();

#pragma unroll
        for (int ks = 0; ks < 2; ks++) {
            uint32_t ahf[4][4], alf[4][4], bhf[2][4], blf[2][4];
            const int ac = ks * 2 + ac_l;
#pragma unroll
            for (int mt = 0; mt < 4; mt++) {
                const uint32_t so = sw_off(arow_l + 16 * mt, ac);
                LDSM_X4(ahf[mt][0], ahf[mt][1], ahf[mt][2], ahf[mt][3], sbuf + so);
                LDSM_X4(alf[mt][0], alf[mt][1], alf[mt][2], alf[mt][3], sbuf + 8192 + so);
            }
            const int bc = ks * 2 + bc_l;
#pragma unroll
            for (int np = 0; np < 2; np++) {
                const uint32_t so = sw_off(brow_l + 16 * np, bc);
                LDSM_X4(bhf[np][0], bhf[np][1], bhf[np][2], bhf[np][3], sbuf + 16384 + so);
                LDSM_X4(blf[np][0], blf[np][1], blf[np][2], blf[np][3], sbuf + 24576 + so);
            }
#pragma unroll
            for (int mt = 0; mt < 4; mt++) {
#pragma unroll
                for (int nt = 0; nt < 4; nt++) {
                    const int np = nt >> 1;
                    const int q  = (nt & 1) * 2;
                    MMA_BF16(acc[mt][nt], ahf[mt], bhf[np][q], bhf[np][q + 1]);
                    MMA_BF16(acc[mt][nt], ahf[mt], blf[np][q], blf[np][q + 1]);
                    MMA_BF16(acc[mt][nt], alf[mt], bhf[np][q], bhf[np][q + 1]);
                }
            }
        }
        __syncthreads();
    }

    const int mbase = m0 + warpM * 64;
#pragma unroll
    for (int nt = 0; nt < 4; nt++) {
        const int col = n0 + warpN * 32 + nt * 8 + 2 * (lane & 3);
        const float b0 = bias[col];
        const float b1 = bias[col + 1];
#pragma unroll
        for (int mt = 0; mt < 4; mt++) {
            const int r0 = mbase + mt * 16 + (lane >> 2);
#pragma unroll
            for (int half = 0; half < 2; half++) {
                const int m = r0 + half * 8;
                const float vx = acc[mt][nt][half * 2 + 0] + b0;
                const float vy = acc[mt][nt][half * 2 + 1] + b1;
                if (HS) {
                    const int b_ = m >> 11;
                    const int s_ = m & (SEQ - 1);
                    const int h  = col >> 6;
                    const int dk = col & 63;
                    const size_t idx = ((((size_t)b_ * HEADS + h) * SEQ) + s_) * DK + dk;
                    uint32_t hw, lw;
                    split2(vx, vy, hw, lw);
                    *(uint32_t*)(Ch + idx) = hw;
                    *(uint32_t*)(Cl + idx) = lw;
                } else {
                    float2 o = make_float2(vx, vy);
                    *(float2*)(Cf + (size_t)m * DM + col) = o;
                }
            }
        }
    }
}

// ---------------------------------------------------------------------------
// Flash attention on mma.sync bf16x3.
// Block: 128 threads = 4 warps, BQ=64 (16 rows/warp), BK=64, DK=64.
// SMEM: 2 stages x (Kh|Kl|Vh|Vl), each 64x64 bf16 = 8 KB -> 32 KB/stage.
// Row swizzle: chunk' = chunk ^ (row & 7) within 128B rows (8 x 16B chunks).
// ---------------------------------------------------------------------------
#define ATTN_SMEM_BYTES 65536

__device__ __forceinline__ uint32_t off8(int row, int chunk)
{
    return (uint32_t)((row * 8 + (chunk ^ (row & 7))) * 16);
}

__global__ void __launch_bounds__(128) attn_mma_kernel()
{
    extern __shared__ char smem[];
    const uint32_t sbase = smem_to_u32(smem);
    const int tid  = threadIdx.x;
    const int lane = tid & 31;
    const int warp = tid >> 5;
    const int b    = blockIdx.z;
    const int h    = blockIdx.y;
    const int q0   = blockIdx.x * 64;

    const size_t bh = (size_t)(b * HEADS + h) * SEQ * DK;
    const __nv_bfloat16* Qhg = g_Qh + bh;
    const __nv_bfloat16* Qlg = g_Ql + bh;
    const __nv_bfloat16* Khg = g_Kh + bh;
    const __nv_bfloat16* Klg = g_Kl + bh;
    const __nv_bfloat16* Vhg = g_Vh + bh;
    const __nv_bfloat16* Vlg = g_Vl + bh;

    // ---- stage Q through smem once, keep fragments in registers ----
#pragma unroll
    for (int i = 0; i < 4; i++) {
        const int idx = tid + i * 128;       // 512 chunks per 8KB tile
        const int row = idx >> 3;
        const int ch  = idx & 7;
        const size_t goff = (size_t)(q0 + row) * DK + ch * 8;
        CP_ASYNC16(sbase + off8(row, ch),        Qhg + goff);
        CP_ASYNC16(sbase + 8192 + off8(row, ch), Qlg + goff);
    }
    CP_COMMIT();
    CP_WAIT0();
    __syncthreads();

    uint32_t qfh[4][4], qfl[4][4];
    const int qrow_l = warp * 16 + (lane & 15);
#pragma unroll
    for (int ks = 0; ks < 4; ks++) {
        const int ch = ks * 2 + (lane >> 4);
        const uint32_t so = off8(qrow_l, ch);
        LDSM_X4(qfh[ks][0], qfh[ks][1], qfh[ks][2], qfh[ks][3], sbase + so);
        LDSM_X4(qfl[ks][0], qfl[ks][1], qfl[ks][2], qfl[ks][3], sbase + 8192 + so);
    }
    __syncthreads();   // done with Q smem; buffers reused for K/V

    // ---- online softmax state ----
    float acc[8][4];
#pragma unroll
    for (int nt = 0; nt < 8; nt++)
#pragma unroll
        for (int c = 0; c < 4; c++) acc[nt][c] = 0.f;
    float m0 = -1e30f, m1 = -1e30f, l0 = 0.f, l1 = 0.f;

    const int ntiles = q0 / 64 + 1;
    const int dtile  = ntiles - 1;          // diagonal tile index

    // prologue: load KV stage 0
    {
#pragma unroll
        for (int i = 0; i < 4; i++) {
            const int idx = tid + i * 128;
            const int row = idx >> 3;
            const int ch  = idx & 7;
            const size_t goff = (size_t)row * DK + ch * 8;
            const uint32_t so = off8(row, ch);
            CP_ASYNC16(sbase + so,         Khg + goff);
            CP_ASYNC16(sbase + 8192 + so,  Klg + goff);
            CP_ASYNC16(sbase + 16384 + so, Vhg + goff);
            CP_ASYNC16(sbase + 24576 + so, Vlg + goff);
        }
        CP_COMMIT();
    }

    const int krow_l = (lane & 7) + ((lane >> 4) << 3);
    const int kc_l   = ((lane >> 3) & 1);
    const int vrow_l = (lane & 7) + (((lane >> 3) & 1) << 3);
    const int vc_l   = (lane >> 4);
    const int row_g0 = q0 + warp * 16 + (lane >> 2);
    const int row_g1 = row_g0 + 8;

#pragma unroll 1
    for (int t = 0; t < ntiles; t++) {
        const uint32_t sb = sbase + (uint32_t)(t & 1) * 32768u;
        if (t + 1 < ntiles) {
            const uint32_t sn = sbase + (uint32_t)((t + 1) & 1) * 32768u;
#pragma unroll
            for (int i = 0; i < 4; i++) {
                const int idx = tid + i * 128;
                const int row = idx >> 3;
                const int ch  = idx & 7;
                const size_t goff = (size_t)((t + 1) * 64 + row) * DK + ch * 8;
                const uint32_t so = off8(row, ch);
                CP_ASYNC16(sn + so,         Khg + goff);
                CP_ASYNC16(sn + 8192 + so,  Klg + goff);
                CP_ASYNC16(sn + 16384 + so, Vhg + goff);
                CP_ASYNC16(sn + 24576 + so, Vlg + goff);
            }
            CP_COMMIT();
            CP_WAIT1();
        } else {
            CP_WAIT0();
        }
        __syncthreads();

        // ---- scores: S = Qh*Kh + Qh*Kl + Ql*Kh ----
        float sc[8][4];
#pragma unroll
        for (int nt = 0; nt < 8; nt++)
#pragma unroll
            for (int c = 0; c < 4; c++) sc[nt][c] = 0.f;

#pragma unroll
        for (int ks = 0; ks < 4; ks++) {
            uint32_t khf[4][4], klf[4][4];
            const int kc = ks * 2 + kc_l;
#pragma unroll
            for (int np = 0; np < 4; np++) {
                const uint32_t so = off8(np * 16 + krow_l, kc);
                LDSM_X4(khf[np][0], khf[np][1], khf[np][2], khf[np][3], sb + so);
                LDSM_X4(klf[np][0], klf[np][1], klf[np][2], klf[np][3], sb + 8192 + so);
            }
#pragma unroll
            for (int nt = 0; nt < 8; nt++) {
                const int np = nt >> 1;
                const int q  = (nt & 1) * 2;
                MMA_BF16(sc[nt], qfh[ks], khf[np][q], khf[np][q + 1]);
                MMA_BF16(sc[nt], qfh[ks], klf[np][q], klf[np][q + 1]);
                MMA_BF16(sc[nt], qfl[ks], khf[np][q], khf[np][q + 1]);
            }
        }

        // scale + causal mask (diagonal tile only)
        if (t == dtile) {
#pragma unroll
            for (int nt = 0; nt < 8; nt++) {
                const int col = t * 64 + nt * 8 + 2 * (lane & 3);
                sc[nt][0] = (col     <= row_g0) ? sc[nt][0] * 0.125f : -1e30f;
                sc[nt][1] = (col + 1 <= row_g0) ? sc[nt][1] * 0.125f : -1e30f;
                sc[nt][2] = (col     <= row_g1) ? sc[nt][2] * 0.125f : -1e30f;
                sc[nt][3] = (col + 1 <= row_g1) ? sc[nt][3] * 0.125f : -1e30f;
            }
        } else {
#pragma unroll
            for (int nt = 0; nt < 8; nt++)
#pragma unroll
                for (int c = 0; c < 4; c++) sc[nt][c] *= 0.125f;
        }

        // ---- online softmax update ----
        float mn0 = m0, mn1 = m1;
#pragma unroll
        for (int nt = 0; nt < 8; nt++) {
            mn0 = fmaxf(mn0, fmaxf(sc[nt][0], sc[nt][1]));
            mn1 = fmaxf(mn1, fmaxf(sc[nt][2], sc[nt][3]));
        }
        mn0 = fmaxf(mn0, __shfl_xor_sync(0xFFFFFFFF, mn0, 1));
        mn0 = fmaxf(mn0, __shfl_xor_sync(0xFFFFFFFF, mn0, 2));
        mn1 = fmaxf(mn1, __shfl_xor_sync(0xFFFFFFFF, mn1, 1));
        mn1 = fmaxf(mn1, __shfl_xor_sync(0xFFFFFFFF, mn1, 2));

        const float a0 = __expf(m0 - mn0);
        const float a1 = __expf(m1 - mn1);
        m0 = mn0; m1 = mn1;
        l0 *= a0; l1 *= a1;
#pragma unroll
        for (int nt = 0; nt < 8; nt++) {
            acc[nt][0] *= a0; acc[nt][1] *= a0;
            acc[nt][2] *= a1; acc[nt][3] *= a1;
        }

        // exp + split probs into a-fragments (ntile pair 2j,2j+1 = kstep j)
        uint32_t ph[4][4], pl[4][4];
#pragma unroll
        for (int j = 0; j < 4; j++) {
            float p00 = __expf(sc[2 * j][0] - mn0);
            float p01 = __expf(sc[2 * j][1] - mn0);
            float p02 = __expf(sc[2 * j][2] - mn1);
            float p03 = __expf(sc[2 * j][3] - mn1);
            float p10 = __expf(sc[2 * j + 1][0] - mn0);
            float p11 = __expf(sc[2 * j + 1][1] - mn0);
            float p12 = __expf(sc[2 * j + 1][2] - mn1);
            float p13 = __expf(sc[2 * j + 1][3] - mn1);
            l0 += p00 + p01 + p10 + p11;
            l1 += p02 + p03 + p12 + p13;
            split2(p00, p01, ph[j][0], pl[j][0]);
            split2(p02, p03, ph[j][1], pl[j][1]);
            split2(p10, p11, ph[j][2], pl[j][2]);
            split2(p12, p13, ph[j][3], pl[j][3]);
        }

        // ---- PV: O += Ph*Vh + Ph*Vl + Pl*Vh  (V via trans ldmatrix) ----
#pragma unroll
        for (int j = 0; j < 4; j++) {
            uint32_t vhf[4][4], vlf[4][4];
            const int vrow = 16 * j + vrow_l;
#pragma unroll
            for (int np = 0; np < 4; np++) {
                const int ch = 2 * np + vc_l;
                const uint32_t so = off8(vrow, ch);
                LDSM_X4_T(vhf[np][0], vhf[np][1], vhf[np][2], vhf[np][3], sb + 16384 + so);
                LDSM_X4_T(vlf[np][0], vlf[np][1], vlf[np][2], vlf[np][3], sb + 24576 + so);
            }
#pragma unroll
            for (int nt = 0; nt < 8; nt++) {
                const int np = nt >> 1;
                const int q  = (nt & 1) * 2;
                MMA_BF16(acc[nt], ph[j], vhf[np][q], vhf[np][q + 1]);
                MMA_BF16(acc[nt], ph[j], vlf[np][q], vlf[np][q + 1]);
                MMA_BF16(acc[nt], pl[j], vhf[np][q], vhf[np][q + 1]);
            }
        }
        __syncthreads();
    }

    // ---- epilogue: normalize, split to bf16 hi/lo, token-major [tok][DM] ----
    l0 += __shfl_xor_sync(0xFFFFFFFF, l0, 1);
    l0 += __shfl_xor_sync(0xFFFFFFFF, l0, 2);
    l1 += __shfl_xor_sync(0xFFFFFFFF, l1, 1);
    l1 += __shfl_xor_sync(0xFFFFFFFF, l1, 2);
    const float inv0 = 1.0f / l0;
    const float inv1 = 1.0f / l1;

    const size_t tok0 = (size_t)b * SEQ + row_g0;
    const size_t tok1 = (size_t)b * SEQ + row_g1;
#pragma unroll
    for (int nt = 0; nt < 8; nt++) {
        const int col = h * DK + nt * 8 + 2 * (lane & 3);
        uint32_t hw, lw;
        split2(acc[nt][0] * inv0, acc[nt][1] * inv0, hw, lw);
        *(uint32_t*)(g_oh + tok0 * DM + col) = hw;
        *(uint32_t*)(g_ol + tok0 * DM + col) = lw;
        split2(acc[nt][2] * inv1, acc[nt][3] * inv1, hw, lw);
        *(uint32_t*)(g_oh + tok1 * DM + col) = hw;
        *(uint32_t*)(g_ol + tok1 * DM + col) = lw;
    }
}

// ---------------------------------------------------------------------------
// d_in order: 0=q 1=k 2=v 3=mask 4=wq 5=bq 6=wk 7=bk 8=wv 9=bv 10=wo 11=bo
// mask is a known causal tril — handled analytically, not read.
// ---------------------------------------------------------------------------
extern "C" void kernel_launch(void* const* d_in, const int* in_sizes, int n_in,
                              void* d_out, int out_size)
{
    const float* q  = (const float*)d_in[0];
    const float* k  = (const float*)d_in[1];
    const float* v  = (const float*)d_in[2];
    const float* wq = (const float*)d_in[4];
    const float* bq = (const float*)d_in[5];
    const float* wk = (const float*)d_in[6];
    const float* bk = (const float*)d_in[7];
    const float* wv = (const float*)d_in[8];
    const float* bv = (const float*)d_in[9];
    const float* wo = (const float*)d_in[10];
    const float* bo = (const float*)d_in[11];
    float* out = (float*)d_out;

    cudaFuncSetAttribute(gemm_bf3<true>,  cudaFuncAttributeMaxDynamicSharedMemorySize, GEMM_SMEM_BYTES);
    cudaFuncSetAttribute(gemm_bf3<false>, cudaFuncAttributeMaxDynamicSharedMemorySize, GEMM_SMEM_BYTES);
    cudaFuncSetAttribute(attn_mma_kernel, cudaFuncAttributeMaxDynamicSharedMemorySize, ATTN_SMEM_BYTES);

    __nv_bfloat16 *qh, *ql, *kh, *kl, *vh, *vl, *oh, *ol;
    __nv_bfloat16 *Qh, *Ql, *Kh, *Kl, *Vh, *Vl;
    __nv_bfloat16 *wqh, *wql, *wkh, *wkl, *wvh, *wvl, *woh, *wol;
    cudaGetSymbolAddress((void**)&qh,  g_qh);  cudaGetSymbolAddress((void**)&ql,  g_ql);
    cudaGetSymbolAddress((void**)&kh,  g_kh);  cudaGetSymbolAddress((void**)&kl,  g_kl);
    cudaGetSymbolAddress((void**)&vh,  g_vh);  cudaGetSymbolAddress((void**)&vl,  g_vl);
    cudaGetSymbolAddress((void**)&oh,  g_oh);  cudaGetSymbolAddress((void**)&ol,  g_ol);
    cudaGetSymbolAddress((void**)&Qh,  g_Qh);  cudaGetSymbolAddress((void**)&Ql,  g_Ql);
    cudaGetSymbolAddress((void**)&Kh,  g_Kh);  cudaGetSymbolAddress((void**)&Kl,  g_Kl);
    cudaGetSymbolAddress((void**)&Vh,  g_Vh);  cudaGetSymbolAddress((void**)&Vl,  g_Vl);
    cudaGetSymbolAddress((void**)&wqh, g_wqh); cudaGetSymbolAddress((void**)&wql, g_wql);
    cudaGetSymbolAddress((void**)&wkh, g_wkh); cudaGetSymbolAddress((void**)&wkl, g_wkl);
    cudaGetSymbolAddress((void**)&wvh, g_wvh); cudaGetSymbolAddress((void**)&wvl, g_wvl);
    cudaGetSymbolAddress((void**)&woh, g_woh); cudaGetSymbolAddress((void**)&wol, g_wol);

    const int nAct4 = MTOK * DM / 4;
    const int nW4   = DM * DM / 4;

    split_kernel<<<nAct4 / 256, 256>>>(q,  qh,  ql,  nAct4);
    split_kernel<<<nAct4 / 256, 256>>>(k,  kh,  kl,  nAct4);
    split_kernel<<<nAct4 / 256, 256>>>(v,  vh,  vl,  nAct4);
    split_kernel<<<nW4 / 256, 256>>>(wq, wqh, wql, nW4);
    split_kernel<<<nW4 / 256, 256>>>(wk, wkh, wkl, nW4);
    split_kernel<<<nW4 / 256, 256>>>(wv, wvh, wvl, nW4);
    split_kernel<<<nW4 / 256, 256>>>(wo, woh, wol, nW4);

    dim3 gg(DM / 128, MTOK / 128);     // 8 x 64
    gemm_bf3<true><<<gg, 256, GEMM_SMEM_BYTES>>>(qh, ql, wqh, wql, bq, Qh, Ql, nullptr);
    gemm_bf3<true><<<gg, 256, GEMM_SMEM_BYTES>>>(kh, kl, wkh, wkl, bk, Kh, Kl, nullptr);
    gemm_bf3<true><<<gg, 256, GEMM_SMEM_BYTES>>>(vh, vl, wvh, wvl, bv, Vh, Vl, nullptr);

    dim3 ga(SEQ / 64, HEADS, BATCH);   // 32 x 16 x 4
    attn_mma_kernel<<<ga, 128, ATTN_SMEM_BYTES>>>();

    gemm_bf3<false><<<gg, 256, GEMM_SMEM_BYTES>>>(oh, ol, woh, wol, bo, nullptr, nullptr, out);
}